// round 3
// baseline (speedup 1.0000x reference)
#include <cuda_runtime.h>
#include <cstdint>

// Problem constants
#define BB 8
#define DD 64
#define TT 8192
#define KK 1024
#define NROWS (BB*TT)          // 65536 vectors
#define NZ (BB*DD*TT)          // 4194304 elements of z / z_q
#define THREADS 128
#define NBLOCKS (NROWS/THREADS) // 512
#define CK 64                  // codes per smem chunk

// Scratch (no allocations allowed)
__device__ float g_wnorm[KK];
__device__ float g_partial[NBLOCKS];

// ---- packed f32x2 helpers (sm_103a FFMA2 path; ptxas will not auto-fuse) ----
__device__ __forceinline__ unsigned long long pk2(float lo, float hi) {
    unsigned long long r;
    asm("mov.b64 %0, {%1, %2};" : "=l"(r) : "f"(lo), "f"(hi));
    return r;
}
__device__ __forceinline__ void unpk2(unsigned long long v, float& lo, float& hi) {
    asm("mov.b64 {%0, %1}, %2;" : "=f"(lo), "=f"(hi) : "l"(v));
}
__device__ __forceinline__ unsigned long long fma2(unsigned long long a, unsigned long long b, unsigned long long c) {
    unsigned long long d;
    asm("fma.rn.f32x2 %0, %1, %2, %3;" : "=l"(d) : "l"(a), "l"(b), "l"(c));
    return d;
}
__device__ __forceinline__ unsigned long long mul2(unsigned long long a, unsigned long long b) {
    unsigned long long d;
    asm("mul.rn.f32x2 %0, %1, %2;" : "=l"(d) : "l"(a), "l"(b));
    return d;
}
__device__ __forceinline__ unsigned long long add2(unsigned long long a, unsigned long long b) {
    unsigned long long d;
    asm("add.rn.f32x2 %0, %1, %2;" : "=l"(d) : "l"(a), "l"(b));
    return d;
}

// ---- prep: codebook row norms ||W_k||^2 (tree-sum, deterministic) ----
__global__ void vq_prep_kernel(const float* __restrict__ W) {
    int k = blockIdx.x * blockDim.x + threadIdx.x;
    if (k >= KK) return;
    const float4* wr = reinterpret_cast<const float4*>(W + (size_t)k * DD);
    float sq[64];
#pragma unroll
    for (int j = 0; j < 16; j++) {
        float4 v = wr[j];
        sq[4*j + 0] = __fmul_rn(v.x, v.x);
        sq[4*j + 1] = __fmul_rn(v.y, v.y);
        sq[4*j + 2] = __fmul_rn(v.z, v.z);
        sq[4*j + 3] = __fmul_rn(v.w, v.w);
    }
#pragma unroll
    for (int off = 32; off >= 1; off >>= 1) {
#pragma unroll
        for (int j = 0; j < 32; j++) {
            if (j < off) sq[j] = __fadd_rn(sq[j], sq[j + off]);
        }
    }
    g_wnorm[k] = sq[0];
}

// ---- main: distances + argmin + gather z_q + per-block loss partials ----
__global__ __launch_bounds__(THREADS)
void vq_main_kernel(const float* __restrict__ z,
                    const float* __restrict__ W,
                    float* __restrict__ out_zq,
                    float* __restrict__ out_codes) {
    __shared__ __align__(16) float sW[CK * DD];   // 16 KB codebook chunk
    __shared__ float sWn[CK];
    __shared__ float sRed[THREADS];

    const int tid = threadIdx.x;
    const int row = blockIdx.x * THREADS + tid;
    const int b = row >> 13;        // / TT
    const int t = row & (TT - 1);
    const float* zp = z + (size_t)b * DD * TT + t;

    // Load z row (strided by TT; coalesced across the warp), pack into f32x2,
    // and build ||z||^2 with a binary-tree reduction.
    unsigned long long zz[32];
    float sq[32];
#pragma unroll
    for (int j = 0; j < 32; j++) {
        float v0 = zp[(size_t)(2*j)     * TT];
        float v1 = zp[(size_t)(2*j + 1) * TT];
        zz[j] = pk2(v0, v1);
        sq[j] = __fadd_rn(__fmul_rn(v0, v0), __fmul_rn(v1, v1));
    }
#pragma unroll
    for (int off = 16; off >= 1; off >>= 1) {
#pragma unroll
        for (int j = 0; j < 16; j++) {
            if (j < off) sq[j] = __fadd_rn(sq[j], sq[j + off]);
        }
    }
    const float znorm = sq[0];

    float dmin = 3.4e38f;
    int imin = 0;

    for (int c0 = 0; c0 < KK; c0 += CK) {
        __syncthreads();
        // cooperative chunk load: CK*DD/4 = 1024 float4, 8 per thread
        {
            const float4* src = reinterpret_cast<const float4*>(W + (size_t)c0 * DD);
            float4* dst = reinterpret_cast<float4*>(sW);
#pragma unroll
            for (int i = 0; i < (CK * DD / 4) / THREADS; i++)
                dst[tid + i * THREADS] = src[tid + i * THREADS];
            if (tid < CK) sWn[tid] = g_wnorm[c0 + tid];
        }
        __syncthreads();

        for (int k = 0; k < CK; k++) {
            const ulonglong2* wq = reinterpret_cast<const ulonglong2*>(sW + k * DD);
            ulonglong2 w0 = wq[0];
            ulonglong2 w1 = wq[1];
            unsigned long long a0 = mul2(zz[0], w0.x);
            unsigned long long a1 = mul2(zz[1], w0.y);
            unsigned long long a2 = mul2(zz[2], w1.x);
            unsigned long long a3 = mul2(zz[3], w1.y);
#pragma unroll
            for (int j = 2; j < 16; j += 2) {
                ulonglong2 wa = wq[j];
                ulonglong2 wb = wq[j + 1];
                a0 = fma2(zz[2*j + 0], wa.x, a0);
                a1 = fma2(zz[2*j + 1], wa.y, a1);
                a2 = fma2(zz[2*j + 2], wb.x, a2);
                a3 = fma2(zz[2*j + 3], wb.y, a3);
            }
            a0 = add2(a0, a2);
            a1 = add2(a1, a3);
            a0 = add2(a0, a1);
            float slo, shi;
            unpk2(a0, slo, shi);
            float s = __fadd_rn(slo, shi);
            // distances = (||z||^2 - 2*s) + ||w||^2, rounded per-op like the ref
            float dist = __fadd_rn(__fsub_rn(znorm, __fmul_rn(2.0f, s)), sWn[k]);
            if (dist < dmin) { dmin = dist; imin = c0 + k; }   // first-index wins on ties
        }
    }

    // codes (as float; values 0..1023 exact)
    out_codes[row] = (float)imin;

    // gather winning codebook row -> z_q (layout [B, D, T]) + loss partial
    const float4* wrow = reinterpret_cast<const float4*>(W + (size_t)imin * DD);
    float* oz = out_zq + (size_t)b * DD * TT + t;
    float lsum = 0.0f;
#pragma unroll
    for (int j = 0; j < 16; j++) {
        float4 wv = wrow[j];
        int d = 4 * j;
        float z0, z1, z2, z3;
        unpk2(zz[2*j],     z0, z1);
        unpk2(zz[2*j + 1], z2, z3);
        oz[(size_t)(d + 0) * TT] = wv.x;
        oz[(size_t)(d + 1) * TT] = wv.y;
        oz[(size_t)(d + 2) * TT] = wv.z;
        oz[(size_t)(d + 3) * TT] = wv.w;
        float e0 = wv.x - z0, e1 = wv.y - z1, e2 = wv.z - z2, e3 = wv.w - z3;
        lsum += e0 * e0 + e1 * e1 + e2 * e2 + e3 * e3;
    }

    // deterministic block reduction of loss partials
    sRed[tid] = lsum;
    __syncthreads();
#pragma unroll
    for (int s = THREADS / 2; s > 0; s >>= 1) {
        if (tid < s) sRed[tid] += sRed[tid + s];
        __syncthreads();
    }
    if (tid == 0) g_partial[blockIdx.x] = sRed[0];
}

// ---- finalize: vq_loss = 1.25 * mean((z_q - z)^2) ----
__global__ void vq_finalize_kernel(float* __restrict__ out_loss) {
    __shared__ float sRed[256];
    int tid = threadIdx.x;
    sRed[tid] = g_partial[tid] + g_partial[tid + 256];
    __syncthreads();
#pragma unroll
    for (int s = 128; s > 0; s >>= 1) {
        if (tid < s) sRed[tid] += sRed[tid + s];
        __syncthreads();
    }
    if (tid == 0) out_loss[0] = 1.25f * (sRed[0] / (float)NZ);
}

extern "C" void kernel_launch(void* const* d_in, const int* in_sizes, int n_in,
                              void* d_out, int out_size) {
    const float* z = (const float*)d_in[0];         // [8, 64, 8192]
    const float* W = (const float*)d_in[1];         // [1024, 64]
    float* out = (float*)d_out;
    // Layout: [z_q_st (NZ)] [vq_loss (1)] [codes (NROWS)]
    float* out_zq    = out;
    float* out_loss  = out + NZ;
    float* out_codes = out + NZ + 1;

    vq_prep_kernel<<<8, 128>>>(W);
    vq_main_kernel<<<NBLOCKS, THREADS>>>(z, W, out_zq, out_codes);
    vq_finalize_kernel<<<1, 256>>>(out_loss);
}

// round 5
// speedup vs baseline: 3.3483x; 3.3483x over previous
#include <cuda_runtime.h>
#include <cuda_bf16.h>
#include <cstdint>

// ---------------- problem constants ----------------
#define BB 8
#define DD 64
#define TT 8192
#define KK 1024
#define NROWS 65536
#define NZ 4194304
#define THREADS 128
#define NBLOCKS 512
#define NC 64                 // codes per chunk
#define NCHUNKS 16

// ---------------- device scratch (no allocs allowed) ----------------
__device__ float g_wnorm[KK];
__device__ float g_partial[NBLOCKS];
__device__ __align__(16) __nv_bfloat16 g_wh[KK * DD];
__device__ __align__(16) __nv_bfloat16 g_wl[KK * DD];

// ---------------- static SMEM layout ----------------
#define B_ROW_STRIDE 144              // 128B data + 16B pad -> conflict-free b-frag LDS
#define B_PART (64 * B_ROW_STRIDE)    // 9216 B per (chunk, hi/lo part)
#define B_BUF  (2 * B_PART)           // 18432 B per buffer (hi+lo)
#define SM_B    0                     // 2 buffers: 36864 B  (also reused for z staging)
#define SM_WN   36864                 // wnorm[1024] fp32: 4096 B
#define SM_ZN   40960                 // znorm[128]: 512 B
#define SM_RED  41472                 // loss reduction[128]: 512 B
#define SM_SIZE 41984

// ---------------- helpers ----------------
__device__ __forceinline__ uint32_t smem_u32(const void* p) {
    uint32_t a;
    asm("{ .reg .u64 t; cvta.to.shared.u64 t, %1; cvt.u32.u64 %0, t; }" : "=r"(a) : "l"(p));
    return a;
}
__device__ __forceinline__ void cp_async16(uint32_t dst, const void* src) {
    asm volatile("cp.async.cg.shared.global [%0], [%1], 16;" :: "r"(dst), "l"(src));
}
#define CP_COMMIT()  asm volatile("cp.async.commit_group;" ::: "memory")
#define CP_WAIT(n)   asm volatile("cp.async.wait_group %0;" :: "n"(n) : "memory")

// m16n8k16 bf16 MMA, fp32 accumulate (sm_80 baseline — no 'a' target needed)
#define MMA_BF16(acc, a, b) \
    asm volatile("mma.sync.aligned.m16n8k16.row.col.f32.bf16.bf16.f32 " \
        "{%0,%1,%2,%3},{%4,%5,%6,%7},{%8,%9},{%0,%1,%2,%3};" \
        : "+f"((acc)[0]), "+f"((acc)[1]), "+f"((acc)[2]), "+f"((acc)[3]) \
        : "r"((a)[0]), "r"((a)[1]), "r"((a)[2]), "r"((a)[3]), \
          "r"((b)[0]), "r"((b)[1]))

__device__ __forceinline__ void split2(float a, float b, uint32_t& h, uint32_t& lo) {
    __nv_bfloat16 ha = __float2bfloat16(a), hb = __float2bfloat16(b);
    float ra = __fsub_rn(a, __bfloat162float(ha));
    float rb = __fsub_rn(b, __bfloat162float(hb));
    __nv_bfloat16 la = __float2bfloat16(ra), lb = __float2bfloat16(rb);
    h  = (uint32_t)__bfloat16_as_ushort(ha) | ((uint32_t)__bfloat16_as_ushort(hb) << 16);
    lo = (uint32_t)__bfloat16_as_ushort(la) | ((uint32_t)__bfloat16_as_ushort(lb) << 16);
}

// ---------------- prep: wnorm (R1-identical order) + bf16 hi/lo split of W ----------------
__global__ void vq_prep_kernel(const float* __restrict__ W) {
    int k = blockIdx.x * blockDim.x + threadIdx.x;
    if (k >= KK) return;
    const float4* wr = reinterpret_cast<const float4*>(W + (size_t)k * DD);
    float sq[64];
#pragma unroll
    for (int j = 0; j < 16; j++) {
        float4 v = wr[j];
        float vv[4] = {v.x, v.y, v.z, v.w};
#pragma unroll
        for (int q = 0; q < 4; q++) {
            float f = vv[q];
            sq[4 * j + q] = __fmul_rn(f, f);
            __nv_bfloat16 h = __float2bfloat16(f);
            float rem = __fsub_rn(f, __bfloat162float(h));
            g_wh[(size_t)k * DD + 4 * j + q] = h;
            g_wl[(size_t)k * DD + 4 * j + q] = __float2bfloat16(rem);
        }
    }
#pragma unroll
    for (int off = 32; off >= 1; off >>= 1) {
#pragma unroll
        for (int j = 0; j < 32; j++) {
            if (j < off) sq[j] = __fadd_rn(sq[j], sq[j + off]);
        }
    }
    g_wnorm[k] = sq[0];
}

// ---------------- chunk prefetch via cp.async ----------------
__device__ __forceinline__ void issue_chunk(uint32_t sb, int chunk, int buf, int tid) {
    const uint4* srcH = reinterpret_cast<const uint4*>(g_wh + (size_t)chunk * NC * DD);
    const uint4* srcL = reinterpret_cast<const uint4*>(g_wl + (size_t)chunk * NC * DD);
    uint32_t dH = sb + SM_B + buf * B_BUF;
    uint32_t dL = dH + B_PART;
#pragma unroll
    for (int i = 0; i < 4; i++) {
        int idx = tid + i * THREADS;          // 0..511 -> row=idx/8, 16B col=idx%8
        uint32_t off = (uint32_t)(idx >> 3) * B_ROW_STRIDE + (uint32_t)(idx & 7) * 16;
        cp_async16(dH + off, srcH + idx);
        cp_async16(dL + off, srcL + idx);
    }
}

// ---------------- per-chunk: 24 HMMA (3 passes) + exact-rounded dist + argmin ----------------
__device__ __forceinline__ void process_chunk(
    const char* smp, int c, int g, int t,
    const uint32_t ah[2][4][4], const uint32_t al[2][4][4],
    const float zn[4], float dmin[4], int imin[4])
{
    const char* bbase = smp + SM_B + (c & 1) * B_BUF;
#pragma unroll
    for (int nt = 0; nt < 8; nt++) {
        const char* rowp = bbase + (nt * 8 + g) * B_ROW_STRIDE + 4 * t;
        uint32_t bh[4][2], bl[4][2];
#pragma unroll
        for (int kt = 0; kt < 4; kt++) {
            bh[kt][0] = *reinterpret_cast<const uint32_t*>(rowp + kt * 32);
            bh[kt][1] = *reinterpret_cast<const uint32_t*>(rowp + kt * 32 + 16);
            bl[kt][0] = *reinterpret_cast<const uint32_t*>(rowp + B_PART + kt * 32);
            bl[kt][1] = *reinterpret_cast<const uint32_t*>(rowp + B_PART + kt * 32 + 16);
        }
        float acc[2][4] = {{0.f, 0.f, 0.f, 0.f}, {0.f, 0.f, 0.f, 0.f}};
#pragma unroll
        for (int mt = 0; mt < 2; mt++) {
#pragma unroll
            for (int kt = 0; kt < 4; kt++) MMA_BF16(acc[mt], ah[mt][kt], bh[kt]);  // hh
#pragma unroll
            for (int kt = 0; kt < 4; kt++) MMA_BF16(acc[mt], ah[mt][kt], bl[kt]);  // hl
#pragma unroll
            for (int kt = 0; kt < 4; kt++) MMA_BF16(acc[mt], al[mt][kt], bh[kt]);  // lh
        }
        const int cb = c * 64 + nt * 8 + 2 * t;
        float2 wnv = *reinterpret_cast<const float2*>(smp + SM_WN + (size_t)cb * 4);
#pragma unroll
        for (int mt = 0; mt < 2; mt++) {
            // dist = fadd(fsub(znorm, 2s), wnorm); fma(s,-2,znorm) is bitwise identical (2s exact)
            float d0 = __fadd_rn(__fmaf_rn(acc[mt][0], -2.0f, zn[2 * mt]),     wnv.x);
            float d1 = __fadd_rn(__fmaf_rn(acc[mt][1], -2.0f, zn[2 * mt]),     wnv.y);
            float d2 = __fadd_rn(__fmaf_rn(acc[mt][2], -2.0f, zn[2 * mt + 1]), wnv.x);
            float d3 = __fadd_rn(__fmaf_rn(acc[mt][3], -2.0f, zn[2 * mt + 1]), wnv.y);
            if (d0 < dmin[2 * mt])     { dmin[2 * mt] = d0;     imin[2 * mt] = cb; }
            if (d1 < dmin[2 * mt])     { dmin[2 * mt] = d1;     imin[2 * mt] = cb + 1; }
            if (d2 < dmin[2 * mt + 1]) { dmin[2 * mt + 1] = d2; imin[2 * mt + 1] = cb; }
            if (d3 < dmin[2 * mt + 1]) { dmin[2 * mt + 1] = d3; imin[2 * mt + 1] = cb + 1; }
        }
    }
}

// ---------------- main kernel ----------------
__global__ __launch_bounds__(THREADS)
void vq_main_kernel(const float* __restrict__ z,
                    const float* __restrict__ W,
                    float* __restrict__ out_zq,
                    float* __restrict__ out_codes) {
    __shared__ __align__(16) char smp[SM_SIZE];
    const uint32_t sb = smem_u32(smp);

    const int tid = threadIdx.x;
    const int w = tid >> 5;
    const int l = tid & 31;
    const int g = l >> 2;       // groupID within warp (frag row group)
    const int t = l & 3;        // threadID within group

    // ---- stage z rows into smem (reuses B region) + znorm (R1-identical tree) ----
    {
        const int grow = blockIdx.x * THREADS + tid;
        const float* zp = z + (size_t)(grow >> 13) * DD * TT + (grow & (TT - 1));
        float* zr = reinterpret_cast<float*>(smp) + tid * 65;
        float sq[32];
#pragma unroll
        for (int j = 0; j < 32; j++) {
            float v0 = zp[(size_t)(2 * j) * TT];
            float v1 = zp[(size_t)(2 * j + 1) * TT];
            zr[2 * j] = v0;
            zr[2 * j + 1] = v1;
            sq[j] = __fadd_rn(__fmul_rn(v0, v0), __fmul_rn(v1, v1));
        }
#pragma unroll
        for (int off = 16; off >= 1; off >>= 1) {
#pragma unroll
            for (int j = 0; j < 16; j++) {
                if (j < off) sq[j] = __fadd_rn(sq[j], sq[j + off]);
            }
        }
        reinterpret_cast<float*>(smp + SM_ZN)[tid] = sq[0];
    }
    __syncthreads();

    // ---- build register-resident A fragments (zh, zl) ----
    uint32_t ah[2][4][4], al[2][4][4];
#pragma unroll
    for (int mt = 0; mt < 2; mt++) {
        const float* r0 = reinterpret_cast<const float*>(smp) + (w * 32 + mt * 16 + g) * 65;
        const float* r1 = r0 + 8 * 65;
#pragma unroll
        for (int kt = 0; kt < 4; kt++) {
            const int c0 = kt * 16 + 2 * t;
            split2(r0[c0],     r0[c0 + 1], ah[mt][kt][0], al[mt][kt][0]);
            split2(r1[c0],     r1[c0 + 1], ah[mt][kt][1], al[mt][kt][1]);
            split2(r0[c0 + 8], r0[c0 + 9], ah[mt][kt][2], al[mt][kt][2]);
            split2(r1[c0 + 8], r1[c0 + 9], ah[mt][kt][3], al[mt][kt][3]);
        }
    }
    float zn[4];
#pragma unroll
    for (int s = 0; s < 4; s++)
        zn[s] = reinterpret_cast<const float*>(smp + SM_ZN)[w * 32 + g + 8 * s];
    __syncthreads();   // z staging region now free -> becomes B buffers

    // ---- prefetch chunks 0,1; load wnorm table ----
    issue_chunk(sb, 0, 0, tid); CP_COMMIT();
    issue_chunk(sb, 1, 1, tid); CP_COMMIT();
    {
        float* sWN = reinterpret_cast<float*>(smp + SM_WN);
#pragma unroll
        for (int i = 0; i < KK / THREADS; i++)
            sWN[tid + i * THREADS] = g_wnorm[tid + i * THREADS];
    }

    float dmin[4] = {3.4e38f, 3.4e38f, 3.4e38f, 3.4e38f};
    int imin[4] = {0, 0, 0, 0};

    // ---- main pipeline ----
    for (int c = 0; c < NCHUNKS - 1; c++) {
        CP_WAIT(1);            // chunk c ready (FIFO group completion)
        __syncthreads();
        process_chunk(smp, c, g, t, ah, al, zn, dmin, imin);
        __syncthreads();       // all warps done reading buf (c&1)
        if (c < NCHUNKS - 2) { issue_chunk(sb, c + 2, c & 1, tid); CP_COMMIT(); }
    }
    CP_WAIT(0);
    __syncthreads();
    process_chunk(smp, NCHUNKS - 1, g, t, ah, al, zn, dmin, imin);

    // ---- cross-lane reduce over the t-quad (smaller index wins ties) ----
#pragma unroll
    for (int s = 0; s < 4; s++) {
#pragma unroll
        for (int o = 1; o < 4; o <<= 1) {
            float od = __shfl_xor_sync(0xffffffff, dmin[s], o);
            int   oi = __shfl_xor_sync(0xffffffff, imin[s], o);
            if (od < dmin[s] || (od == dmin[s] && oi < imin[s])) { dmin[s] = od; imin[s] = oi; }
        }
    }
    const int my = (t == 0) ? imin[0] : (t == 1) ? imin[1] : (t == 2) ? imin[2] : imin[3];

    // ---- outputs: codes, z_q_st = z + (w - z), loss partial ----
    const int rown = w * 32 + g + 8 * t;         // each thread owns one distinct row
    const int grow = blockIdx.x * THREADS + rown;
    out_codes[grow] = (float)my;

    const int b = grow >> 13;
    const int tp = grow & (TT - 1);
    const float* zp = z + (size_t)b * DD * TT + tp;
    float* oz = out_zq + (size_t)b * DD * TT + tp;
    const float4* wrow = reinterpret_cast<const float4*>(W + (size_t)my * DD);
    float lsum = 0.0f;
#pragma unroll
    for (int j = 0; j < 16; j++) {
        float4 wv = wrow[j];
        float wa[4] = {wv.x, wv.y, wv.z, wv.w};
#pragma unroll
        for (int q = 0; q < 4; q++) {
            float zv = zp[(size_t)(4 * j + q) * TT];
            float e = __fsub_rn(wa[q], zv);
            oz[(size_t)(4 * j + q) * TT] = __fadd_rn(zv, e);   // straight-through estimator
            lsum = __fadd_rn(lsum, __fmul_rn(e, e));
        }
    }

    float* sRed = reinterpret_cast<float*>(smp + SM_RED);
    sRed[tid] = lsum;
    __syncthreads();
#pragma unroll
    for (int s = THREADS / 2; s > 0; s >>= 1) {
        if (tid < s) sRed[tid] += sRed[tid + s];
        __syncthreads();
    }
    if (tid == 0) g_partial[blockIdx.x] = sRed[0];
}

// ---------------- finalize: vq_loss = 1.25 * mean((z_q - z)^2) ----------------
__global__ void vq_finalize_kernel(float* __restrict__ out_loss) {
    __shared__ float sRed[256];
    int tid = threadIdx.x;
    sRed[tid] = g_partial[tid] + g_partial[tid + 256];
    __syncthreads();
#pragma unroll
    for (int s = 128; s > 0; s >>= 1) {
        if (tid < s) sRed[tid] += sRed[tid + s];
        __syncthreads();
    }
    if (tid == 0) out_loss[0] = 1.25f * (sRed[0] / (float)NZ);
}

extern "C" void kernel_launch(void* const* d_in, const int* in_sizes, int n_in,
                              void* d_out, int out_size) {
    const float* z = (const float*)d_in[0];      // [8, 64, 8192]
    const float* W = (const float*)d_in[1];      // [1024, 64]
    float* out = (float*)d_out;
    float* out_zq    = out;
    float* out_loss  = out + NZ;
    float* out_codes = out + NZ + 1;

    vq_prep_kernel<<<8, 128>>>(W);
    vq_main_kernel<<<NBLOCKS, THREADS>>>(z, W, out_zq, out_codes);
    vq_finalize_kernel<<<1, 256>>>(out_loss);
}

// round 6
// speedup vs baseline: 3.5550x; 1.0617x over previous
#include <cuda_runtime.h>
#include <cuda_bf16.h>
#include <cstdint>

// ---------------- problem constants ----------------
#define BB 8
#define DD 64
#define TT 8192
#define KK 1024
#define NROWS 65536
#define NZ 4194304
#define THREADS 128
#define NBLOCKS 512
#define NC 64                 // codes per chunk
#define NCHUNKS 16

// ---------------- device scratch (no allocs allowed) ----------------
__device__ float g_wnorm[KK];
__device__ float g_partial[NBLOCKS];
__device__ unsigned int g_ticket;     // zero-init; reset by last block every run
__device__ __align__(16) __nv_bfloat16 g_wh[KK * DD];   // fragment-permuted rows
__device__ __align__(16) __nv_bfloat16 g_wl[KK * DD];

// ---------------- static SMEM layout ----------------
#define B_ROW_STRIDE 144              // 128B data + 16B pad -> conflict-free LDS.128
#define B_PART (64 * B_ROW_STRIDE)    // 9216 B per (chunk, hi/lo part)
#define B_BUF  (2 * B_PART)           // 18432 B per buffer (hi+lo)
#define SM_B    0                     // 2 buffers: 36864 B (also reused for z staging)
#define SM_WN   36864                 // wnorm[1024] fp32: 4096 B
#define SM_ZN   40960                 // znorm[128]: 512 B
#define SM_RED  41472                 // loss reduction[128]: 512 B
#define SM_SIZE 41984

// ---------------- helpers ----------------
__device__ __forceinline__ uint32_t smem_u32(const void* p) {
    uint32_t a;
    asm("{ .reg .u64 t; cvta.to.shared.u64 t, %1; cvt.u32.u64 %0, t; }" : "=r"(a) : "l"(p));
    return a;
}
__device__ __forceinline__ void cp_async16(uint32_t dst, const void* src) {
    asm volatile("cp.async.cg.shared.global [%0], [%1], 16;" :: "r"(dst), "l"(src));
}
#define CP_COMMIT()  asm volatile("cp.async.commit_group;" ::: "memory")
#define CP_WAIT(n)   asm volatile("cp.async.wait_group %0;" :: "n"(n) : "memory")

// packed f32x2 (sm_103 packed fp32 pipe)
__device__ __forceinline__ unsigned long long pk2(float lo, float hi) {
    unsigned long long r;
    asm("mov.b64 %0, {%1, %2};" : "=l"(r) : "f"(lo), "f"(hi));
    return r;
}
__device__ __forceinline__ void unpk2(unsigned long long v, float& lo, float& hi) {
    asm("mov.b64 {%0, %1}, %2;" : "=f"(lo), "=f"(hi) : "l"(v));
}
__device__ __forceinline__ unsigned long long fma2(unsigned long long a, unsigned long long b, unsigned long long c) {
    unsigned long long d;
    asm("fma.rn.f32x2 %0, %1, %2, %3;" : "=l"(d) : "l"(a), "l"(b), "l"(c));
    return d;
}
__device__ __forceinline__ unsigned long long add2(unsigned long long a, unsigned long long b) {
    unsigned long long d;
    asm("add.rn.f32x2 %0, %1, %2;" : "=l"(d) : "l"(a), "l"(b));
    return d;
}

// m16n8k16 bf16 MMA, fp32 accumulate (sm_80 baseline -- no 'a' target needed)
#define MMA_BF16(acc, a, b) \
    asm volatile("mma.sync.aligned.m16n8k16.row.col.f32.bf16.bf16.f32 " \
        "{%0,%1,%2,%3},{%4,%5,%6,%7},{%8,%9},{%0,%1,%2,%3};" \
        : "+f"((acc)[0]), "+f"((acc)[1]), "+f"((acc)[2]), "+f"((acc)[3]) \
        : "r"((a)[0]), "r"((a)[1]), "r"((a)[2]), "r"((a)[3]), \
          "r"((b)[0]), "r"((b)[1]))

__device__ __forceinline__ void split2(float a, float b, uint32_t& h, uint32_t& lo) {
    __nv_bfloat16 ha = __float2bfloat16(a), hb = __float2bfloat16(b);
    float ra = __fsub_rn(a, __bfloat162float(ha));
    float rb = __fsub_rn(b, __bfloat162float(hb));
    __nv_bfloat16 la = __float2bfloat16(ra), lb = __float2bfloat16(rb);
    h  = (uint32_t)__bfloat16_as_ushort(ha) | ((uint32_t)__bfloat16_as_ushort(hb) << 16);
    lo = (uint32_t)__bfloat16_as_ushort(la) | ((uint32_t)__bfloat16_as_ushort(lb) << 16);
}

// fragment permutation: element kk (0..63) of a W row -> bf16 slot
// kk = kt*16 + half*8 + 2*t + e  ->  idx = t*16 + kt*4 + half*2 + e
__device__ __host__ __forceinline__ int permidx(int kk) {
    int kt = kk >> 4, r = kk & 15;
    int half = r >> 3, s = r & 7, tq = s >> 1, e = s & 1;
    return tq * 16 + kt * 4 + half * 2 + e;
}

// ---------------- prep: wnorm (R1-identical rounding order) + permuted bf16 split ----------------
__global__ void vq_prep_kernel(const float* __restrict__ W) {
    int k = blockIdx.x * blockDim.x + threadIdx.x;   // 1024 threads total
    if (k >= KK) return;
    const float4* wr = reinterpret_cast<const float4*>(W + (size_t)k * DD);
    float t32[32];
    uint32_t uh[32], ul[32];
#pragma unroll
    for (int i = 0; i < 32; i++) { uh[i] = 0; ul[i] = 0; }
#pragma unroll
    for (int j = 0; j < 8; j++) {
        float4 va = wr[j];          // elements 4j..4j+3
        float4 vb = wr[j + 8];      // elements 4j+32..4j+35
        float av[4] = {va.x, va.y, va.z, va.w};
        float bv[4] = {vb.x, vb.y, vb.z, vb.w};
#pragma unroll
        for (int q = 0; q < 4; q++) {
            // matches R1 tree level off=32: fadd(sq[j], sq[j+32]) with sq = fmul(w,w)
            t32[4 * j + q] = __fadd_rn(__fmul_rn(av[q], av[q]), __fmul_rn(bv[q], bv[q]));
            {
                int idx = permidx(4 * j + q);
                __nv_bfloat16 h = __float2bfloat16(av[q]);
                __nv_bfloat16 l = __float2bfloat16(__fsub_rn(av[q], __bfloat162float(h)));
                uh[idx >> 1] |= (uint32_t)__bfloat16_as_ushort(h) << (16 * (idx & 1));
                ul[idx >> 1] |= (uint32_t)__bfloat16_as_ushort(l) << (16 * (idx & 1));
            }
            {
                int idx = permidx(4 * j + q + 32);
                __nv_bfloat16 h = __float2bfloat16(bv[q]);
                __nv_bfloat16 l = __float2bfloat16(__fsub_rn(bv[q], __bfloat162float(h)));
                uh[idx >> 1] |= (uint32_t)__bfloat16_as_ushort(h) << (16 * (idx & 1));
                ul[idx >> 1] |= (uint32_t)__bfloat16_as_ushort(l) << (16 * (idx & 1));
            }
        }
    }
#pragma unroll
    for (int off = 16; off >= 1; off >>= 1) {
#pragma unroll
        for (int j = 0; j < 16; j++) {
            if (j < off) t32[j] = __fadd_rn(t32[j], t32[j + off]);
        }
    }
    g_wnorm[k] = t32[0];
    uint4* dh = reinterpret_cast<uint4*>(g_wh + (size_t)k * DD);
    uint4* dl = reinterpret_cast<uint4*>(g_wl + (size_t)k * DD);
#pragma unroll
    for (int i = 0; i < 8; i++) {
        dh[i] = make_uint4(uh[4 * i], uh[4 * i + 1], uh[4 * i + 2], uh[4 * i + 3]);
        dl[i] = make_uint4(ul[4 * i], ul[4 * i + 1], ul[4 * i + 2], ul[4 * i + 3]);
    }
}

// ---------------- chunk prefetch via cp.async ----------------
__device__ __forceinline__ void issue_chunk(uint32_t sb, int chunk, int buf, int tid) {
    const uint4* srcH = reinterpret_cast<const uint4*>(g_wh + (size_t)chunk * NC * DD);
    const uint4* srcL = reinterpret_cast<const uint4*>(g_wl + (size_t)chunk * NC * DD);
    uint32_t dH = sb + SM_B + buf * B_BUF;
    uint32_t dL = dH + B_PART;
#pragma unroll
    for (int i = 0; i < 4; i++) {
        int idx = tid + i * THREADS;          // 0..511 -> row=idx/8, 16B col=idx%8
        uint32_t off = (uint32_t)(idx >> 3) * B_ROW_STRIDE + (uint32_t)(idx & 7) * 16;
        cp_async16(dH + off, srcH + idx);
        cp_async16(dL + off, srcL + idx);
    }
}

// ---------------- per-chunk: 24 HMMA x 8nt + packed dist + argmin ----------------
__device__ __forceinline__ void process_chunk(
    const char* smp, int c, int g, int t,
    const uint32_t ah[2][4][4], const uint32_t al[2][4][4],
    const unsigned long long zpkA[2], const unsigned long long zpkB[2],
    unsigned long long NEG2, float dmin[4], int imin[4])
{
    const char* bbase = smp + SM_B + (c & 1) * B_BUF;
#pragma unroll
    for (int nt = 0; nt < 8; nt++) {
        const char* rowp = bbase + (nt * 8 + g) * B_ROW_STRIDE + t * 32;
        uint4 h0 = *reinterpret_cast<const uint4*>(rowp);
        uint4 h1 = *reinterpret_cast<const uint4*>(rowp + 16);
        uint4 l0 = *reinterpret_cast<const uint4*>(rowp + B_PART);
        uint4 l1 = *reinterpret_cast<const uint4*>(rowp + B_PART + 16);
        uint32_t bh[4][2] = {{h0.x, h0.y}, {h0.z, h0.w}, {h1.x, h1.y}, {h1.z, h1.w}};
        uint32_t bl[4][2] = {{l0.x, l0.y}, {l0.z, l0.w}, {l1.x, l1.y}, {l1.z, l1.w}};
        float acc[2][4] = {{0.f, 0.f, 0.f, 0.f}, {0.f, 0.f, 0.f, 0.f}};
#pragma unroll
        for (int mt = 0; mt < 2; mt++) {
#pragma unroll
            for (int kt = 0; kt < 4; kt++) MMA_BF16(acc[mt], ah[mt][kt], bh[kt]);  // hh
#pragma unroll
            for (int kt = 0; kt < 4; kt++) MMA_BF16(acc[mt], ah[mt][kt], bl[kt]);  // hl
#pragma unroll
            for (int kt = 0; kt < 4; kt++) MMA_BF16(acc[mt], al[mt][kt], bh[kt]);  // lh
        }
        const int cb = c * 64 + nt * 8 + 2 * t;
        unsigned long long wpk = *reinterpret_cast<const unsigned long long*>(smp + SM_WN + (size_t)cb * 4);
#pragma unroll
        for (int mt = 0; mt < 2; mt++) {
            // per lane: fadd(fma(s, -2, znorm), wn) == fadd(fsub(znorm, 2s), wn) bitwise (2s exact)
            unsigned long long dA = add2(fma2(pk2(acc[mt][0], acc[mt][1]), NEG2, zpkA[mt]), wpk);
            unsigned long long dB = add2(fma2(pk2(acc[mt][2], acc[mt][3]), NEG2, zpkB[mt]), wpk);
            float d0, d1, d2, d3;
            unpk2(dA, d0, d1);
            unpk2(dB, d2, d3);
            if (d0 < dmin[2 * mt])     { dmin[2 * mt] = d0;     imin[2 * mt] = cb; }
            if (d1 < dmin[2 * mt])     { dmin[2 * mt] = d1;     imin[2 * mt] = cb + 1; }
            if (d2 < dmin[2 * mt + 1]) { dmin[2 * mt + 1] = d2; imin[2 * mt + 1] = cb; }
            if (d3 < dmin[2 * mt + 1]) { dmin[2 * mt + 1] = d3; imin[2 * mt + 1] = cb + 1; }
        }
    }
}

// ---------------- main kernel (finalize fused via last-block ticket) ----------------
__global__ __launch_bounds__(THREADS, 4)
void vq_main_kernel(const float* __restrict__ z,
                    const float* __restrict__ W,
                    float* __restrict__ out_zq,
                    float* __restrict__ out_codes,
                    float* __restrict__ out_loss) {
    __shared__ __align__(16) char smp[SM_SIZE];
    const uint32_t sb = smem_u32(smp);

    const int tid = threadIdx.x;
    const int w = tid >> 5;
    const int l = tid & 31;
    const int g = l >> 2;
    const int t = l & 3;

    // ---- stage z rows into smem (reuses B region) + znorm (R1-identical tree) ----
    {
        const int grow = blockIdx.x * THREADS + tid;
        const float* zp = z + (size_t)(grow >> 13) * DD * TT + (grow & (TT - 1));
        float* zr = reinterpret_cast<float*>(smp) + tid * 65;
        float sq[32];
#pragma unroll
        for (int j = 0; j < 32; j++) {
            float v0 = zp[(size_t)(2 * j) * TT];
            float v1 = zp[(size_t)(2 * j + 1) * TT];
            zr[2 * j] = v0;
            zr[2 * j + 1] = v1;
            sq[j] = __fadd_rn(__fmul_rn(v0, v0), __fmul_rn(v1, v1));
        }
#pragma unroll
        for (int off = 16; off >= 1; off >>= 1) {
#pragma unroll
            for (int j = 0; j < 16; j++) {
                if (j < off) sq[j] = __fadd_rn(sq[j], sq[j + off]);
            }
        }
        reinterpret_cast<float*>(smp + SM_ZN)[tid] = sq[0];
    }
    __syncthreads();

    // ---- register-resident A fragments (zh, zl) ----
    uint32_t ah[2][4][4], al[2][4][4];
#pragma unroll
    for (int mt = 0; mt < 2; mt++) {
        const float* r0 = reinterpret_cast<const float*>(smp) + (w * 32 + mt * 16 + g) * 65;
        const float* r1 = r0 + 8 * 65;
#pragma unroll
        for (int kt = 0; kt < 4; kt++) {
            const int c0 = kt * 16 + 2 * t;
            split2(r0[c0],     r0[c0 + 1], ah[mt][kt][0], al[mt][kt][0]);
            split2(r1[c0],     r1[c0 + 1], ah[mt][kt][1], al[mt][kt][1]);
            split2(r0[c0 + 8], r0[c0 + 9], ah[mt][kt][2], al[mt][kt][2]);
            split2(r1[c0 + 8], r1[c0 + 9], ah[mt][kt][3], al[mt][kt][3]);
        }
    }
    unsigned long long zpkA[2], zpkB[2];
#pragma unroll
    for (int mt = 0; mt < 2; mt++) {
        float a = reinterpret_cast<const float*>(smp + SM_ZN)[w * 32 + g + 8 * (2 * mt)];
        float b = reinterpret_cast<const float*>(smp + SM_ZN)[w * 32 + g + 8 * (2 * mt + 1)];
        zpkA[mt] = pk2(a, a);
        zpkB[mt] = pk2(b, b);
    }
    const unsigned long long NEG2 = pk2(-2.0f, -2.0f);
    __syncthreads();   // z staging region now free -> becomes B buffers

    // ---- prefetch chunks 0,1; load wnorm table ----
    issue_chunk(sb, 0, 0, tid); CP_COMMIT();
    issue_chunk(sb, 1, 1, tid); CP_COMMIT();
    {
        float* sWN = reinterpret_cast<float*>(smp + SM_WN);
#pragma unroll
        for (int i = 0; i < KK / THREADS; i++)
            sWN[tid + i * THREADS] = g_wnorm[tid + i * THREADS];
    }

    float dmin[4] = {3.4e38f, 3.4e38f, 3.4e38f, 3.4e38f};
    int imin[4] = {0, 0, 0, 0};

    // ---- main pipeline ----
    for (int c = 0; c < NCHUNKS - 1; c++) {
        CP_WAIT(1);
        __syncthreads();
        process_chunk(smp, c, g, t, ah, al, zpkA, zpkB, NEG2, dmin, imin);
        __syncthreads();
        if (c < NCHUNKS - 2) { issue_chunk(sb, c + 2, c & 1, tid); CP_COMMIT(); }
    }
    CP_WAIT(0);
    __syncthreads();
    process_chunk(smp, NCHUNKS - 1, g, t, ah, al, zpkA, zpkB, NEG2, dmin, imin);

    // ---- cross-lane reduce over the t-quad (smaller index wins ties) ----
#pragma unroll
    for (int s = 0; s < 4; s++) {
#pragma unroll
        for (int o = 1; o < 4; o <<= 1) {
            float od = __shfl_xor_sync(0xffffffff, dmin[s], o);
            int   oi = __shfl_xor_sync(0xffffffff, imin[s], o);
            if (od < dmin[s] || (od == dmin[s] && oi < imin[s])) { dmin[s] = od; imin[s] = oi; }
        }
    }
    const int my = (t == 0) ? imin[0] : (t == 1) ? imin[1] : (t == 2) ? imin[2] : imin[3];

    // ---- outputs: codes, z_q_st = z + (w - z), loss partial ----
    const int rown = w * 32 + g + 8 * t;
    const int grow = blockIdx.x * THREADS + rown;
    out_codes[grow] = (float)my;

    const int b = grow >> 13;
    const int tp = grow & (TT - 1);
    const float* zp = z + (size_t)b * DD * TT + tp;
    float* oz = out_zq + (size_t)b * DD * TT + tp;
    const float4* wrow = reinterpret_cast<const float4*>(W + (size_t)my * DD);
    float lsum = 0.0f;
#pragma unroll
    for (int j = 0; j < 16; j++) {
        float4 wv = wrow[j];
        float wa[4] = {wv.x, wv.y, wv.z, wv.w};
#pragma unroll
        for (int q = 0; q < 4; q++) {
            float zv = zp[(size_t)(4 * j + q) * TT];
            float e = __fsub_rn(wa[q], zv);
            oz[(size_t)(4 * j + q) * TT] = __fadd_rn(zv, e);   // straight-through estimator
            lsum = __fadd_rn(lsum, __fmul_rn(e, e));
        }
    }

    float* sRed = reinterpret_cast<float*>(smp + SM_RED);
    sRed[tid] = lsum;
    __syncthreads();
#pragma unroll
    for (int s = THREADS / 2; s > 0; s >>= 1) {
        if (tid < s) sRed[tid] += sRed[tid + s];
        __syncthreads();
    }

    // ---- fused finalize: last block reduces all partials (deterministic order) ----
    __shared__ unsigned int sIsLast;
    if (tid == 0) {
        g_partial[blockIdx.x] = sRed[0];
        __threadfence();
        unsigned int tk = atomicAdd(&g_ticket, 1u);
        sIsLast = (tk == NBLOCKS - 1) ? 1u : 0u;
    }
    __syncthreads();
    if (sIsLast) {
        float v = __fadd_rn(__fadd_rn(g_partial[tid], g_partial[tid + 128]),
                            __fadd_rn(g_partial[tid + 256], g_partial[tid + 384]));
        sRed[tid] = v;
        __syncthreads();
#pragma unroll
        for (int s = THREADS / 2; s > 0; s >>= 1) {
            if (tid < s) sRed[tid] += sRed[tid + s];
            __syncthreads();
        }
        if (tid == 0) {
            out_loss[0] = 1.25f * (sRed[0] / (float)NZ);
            g_ticket = 0;    // reset for next graph replay
        }
    }
}

extern "C" void kernel_launch(void* const* d_in, const int* in_sizes, int n_in,
                              void* d_out, int out_size) {
    const float* z = (const float*)d_in[0];      // [8, 64, 8192]
    const float* W = (const float*)d_in[1];      // [1024, 64]
    float* out = (float*)d_out;
    float* out_zq    = out;
    float* out_loss  = out + NZ;
    float* out_codes = out + NZ + 1;

    vq_prep_kernel<<<32, 32>>>(W);
    vq_main_kernel<<<NBLOCKS, THREADS>>>(z, W, out_zq, out_codes, out_loss);
}